// round 16
// baseline (speedup 1.0000x reference)
#include <cuda_runtime.h>
#include <cstdint>

#define BB 32
#define T_IN 512
#define NT 426
#define NP 213           // NT/2 pairs
#define NC 1629          // 543*3
#define JF 53
#define XPART ((size_t)BB * NT * NC)   // 22,206,528
#define NCHUNK 7         // 7*256 = 1792 >= 1629
#define MAXU 16          // max union rows per pair

__device__ __forceinline__ bool read_bool_m(const void* p, int i, int m) {
    if (m == 0) return ((const unsigned char*)p)[i] != 0;
    if (m == 1) return ((const int*)p)[i] != 0;
    return ((const float*)p)[i] != 0.0f;
}

// Single kernel, one block per (b, pair p): t0=2p, t1=2p+1.
//  phase 0: dtype detect (128-word window, L2-hot)
//  phase 1: thread 0 checks keep[t0-1], keep[t0], keep[t1]
//  phase 2 (only if any dropped, ~27% of blocks): 2-round ballot scan of this
//           batch's keep mask -> kept list in shared
//  phase 3: thread 0 builds merged (row, w_t0, w_t1) union list in shared +
//           mask outputs
//  phase 4: streaming pass (R15 body): each x value loaded once, feeds two
//           FMA chains. out = sum_i w_i * x[row_i] + noise*.01 + spatial*.005
__global__ __launch_bounds__(256) void fused_kernel(
    const float* __restrict__ x,
    const void*  __restrict__ mask,
    const void*  __restrict__ keep,
    const float* __restrict__ bj,
    const float* __restrict__ noise,
    const float* __restrict__ sp,
    float* __restrict__ out)
{
    __shared__ int   s_bad, s_anyf, s_mode, s_need;
    __shared__ int   s_kept[NT];
    __shared__ int   s_K;
    __shared__ int   wsum[16];
    __shared__ int   srows[MAXU];
    __shared__ float sw0[MAXU], sw1[MAXU];
    __shared__ int   snum;

    const int bp  = blockIdx.x;
    const int b   = bp / NP;
    const int p   = bp - b * NP;
    const int t0  = 2 * p;
    const int t1  = t0 + 1;
    const int tid = threadIdx.x;

    // ---- phase 0: dtype detection ----
    if (tid == 0) { s_bad = 0; s_anyf = 0; }
    __syncthreads();
    if (tid < 128) {
        unsigned v = ((const unsigned*)keep)[tid];
        if (v != 0u && v != 1u) atomicOr(&s_bad, 1);
        if (v == 0x3F800000u)   atomicOr(&s_anyf, 1);
    }
    __syncthreads();
    // ---- phase 1: does this pair need the kept-prefix list? ----
    if (tid == 0) {
        int m = s_bad ? (s_anyf ? 2 : 0) : 1;
        s_mode = m;
        bool k0 = read_bool_m(keep, b * NT + t0, m);
        bool k1 = read_bool_m(keep, b * NT + t1, m);
        bool km = (t0 > 0) ? read_bool_m(keep, b * NT + t0 - 1, m) : true;
        s_need = !(k0 && k1 && km);
    }
    __syncthreads();
    const int m = s_mode;

    // ---- phase 2: ballot scan (slow path only) ----
    if (s_need) {
        int lane = tid & 31, wid = tid >> 5;
        bool ka = read_bool_m(keep, b * NT + tid, m);          // t = 0..255
        unsigned bal0 = __ballot_sync(0xFFFFFFFFu, ka);
        if (lane == 0) wsum[wid] = __popc(bal0);
        int tB = 256 + tid;                                     // t = 256..425
        bool kc = (tB < NT) ? read_bool_m(keep, b * NT + tB, m) : false;
        unsigned bal1 = __ballot_sync(0xFFFFFFFFu, kc);
        if (lane == 0) wsum[8 + wid] = __popc(bal1);
        __syncthreads();
        int pre0 = __popc(bal0 & ((1u << lane) - 1u));
        int pre1 = __popc(bal1 & ((1u << lane) - 1u));
        int base0 = 0, base1 = 0;
        for (int i = 0; i < wid; i++)     base0 += wsum[i];
        for (int i = 0; i < 8 + wid; i++) base1 += wsum[i];
        if (ka) s_kept[base0 + pre0] = tid;
        if (kc) s_kept[base1 + pre1] = tB;
        if (tid == 0) {
            int K = 0;
            for (int i = 0; i < 16; i++) K += wsum[i];
            s_K = K;
        }
        __syncthreads();
    }

    // ---- phase 3: thread 0 builds union list in shared ----
    if (tid == 0) {
        int K = s_need ? s_K : 0;   // only read on slow path
        int nU = 0;

        auto pushU = [&](int r, float w, int which) {
            for (int i = 0; i < nU; i++)
                if (srows[i] == r) { if (which) sw1[i] += w; else sw0[i] += w; return; }
            srows[nU] = r;
            sw0[nU] = which ? 0.0f : w;
            sw1[nU] = which ? w : 0.0f;
            nU++;
        };
        auto add_x1 = [&](int tau, float c, int which) {
            float s = (float)tau * (511.0f / 425.0f);
            int i0 = (int)floorf(s);
            if (i0 > T_IN - 2) i0 = T_IN - 2;
            if (i0 < 0) i0 = 0;
            float f = s - (float)i0;
            pushU(i0,     c * (1.0f - f), which);
            pushU(i0 + 1, c * f,          which);
        };
        auto add_x2 = [&](int tau, float c, int which) {
            if (read_bool_m(keep, b * NT + tau, m)) {
                add_x1(tau, c, which);
            } else {
                float s = ((float)tau * (float)(K - 1)) / 425.0f;
                int r0 = (int)floorf(s);
                if (r0 > K - 2) r0 = K - 2;
                if (r0 < 0) r0 = 0;
                float fd = s - (float)r0;
                add_x1(s_kept[r0],     c * (1.0f - fd), which);
                add_x1(s_kept[r0 + 1], c * fd,          which);
            }
        };

        #pragma unroll
        for (int which = 0; which < 2; which++) {
            int t = t0 + which;
            int bt = b * NT + t;
            bool kb = read_bool_m(keep, bt, m);

            // mask output
            int nidx = (int)floorf((float)t * (512.0f / 426.0f));
            if (nidx > T_IN - 1) nidx = T_IN - 1;
            bool mo = read_bool_m(mask, b * T_IN + nidx, m) && kb;
            out[XPART + (size_t)bt] = mo ? 1.0f : 0.0f;

            // jitter (scale-then-lerp matches reference rounding)
            float jit = 0.0f;
            if (t > 0) {
                float sj = (float)t * (52.0f / 425.0f);
                int ij = (int)floorf(sj);
                if (ij > JF - 2) ij = JF - 2;
                if (ij < 0) ij = 0;
                float fj = sj - (float)ij;
                float j0 = bj[b * JF + ij]     * 0.02f;
                float j1 = bj[b * JF + ij + 1] * 0.02f;
                jit = j0 * (1.0f - fj) + j1 * fj;
            }

            if (t == 0) {
                add_x2(0, 1.0f, which);
            } else {
                add_x2(t,     1.0f + jit, which);
                add_x2(t - 1, -jit,       which);
            }
        }
        snum = nU;
    }
    __syncthreads();

    // ---- phase 4: streaming pass (R15 body, proven) ----
    const int n = snum;
    size_t bt0 = (size_t)b * NT + t0;
    const float* xb  = x     + (size_t)b * T_IN * NC;
    const float* nz0 = noise + bt0 * NC;
    const float* nz1 = nz0 + NC;
    const float* sb  = sp    + (size_t)b * NC;
    float*       ob0 = out   + bt0 * NC;
    float*       ob1 = ob0 + NC;

    float acc0[NCHUNK], acc1[NCHUNK];
    #pragma unroll
    for (int k = 0; k < NCHUNK; k++) {
        int e = tid + k * 256;
        float spv = (e < NC) ? sb[e] * 0.005f : 0.0f;
        acc0[k] = (e < NC) ? fmaf(__ldcs(nz0 + e), 0.01f, spv) : 0.0f;
        acc1[k] = (e < NC) ? fmaf(__ldcs(nz1 + e), 0.01f, spv) : 0.0f;
    }

    for (int i = 0; i < n; i++) {
        const float* xr = xb + (size_t)srows[i] * NC;
        float w0 = sw0[i], w1 = sw1[i];
        #pragma unroll
        for (int k = 0; k < NCHUNK; k++) {
            int e = tid + k * 256;
            if (e < NC) {
                float v = __ldg(xr + e);
                acc0[k] = fmaf(w0, v, acc0[k]);
                acc1[k] = fmaf(w1, v, acc1[k]);
            }
        }
    }

    #pragma unroll
    for (int k = 0; k < NCHUNK; k++) {
        int e = tid + k * 256;
        if (e < NC) {
            __stcs(ob0 + e, acc0[k]);
            __stcs(ob1 + e, acc1[k]);
        }
    }
}

extern "C" void kernel_launch(void* const* d_in, const int* in_sizes, int n_in,
                              void* d_out, int out_size) {
    const float* x     = (const float*)d_in[0];
    const void*  mask  = d_in[1];
    const void*  keep  = d_in[2];
    const float* bj    = (const float*)d_in[3];
    const float* noise = (const float*)d_in[4];
    const float* sp    = (const float*)d_in[5];
    float* out = (float*)d_out;

    fused_kernel<<<BB * NP, 256>>>(x, mask, keep, bj, noise, sp, out);
}